// round 4
// baseline (speedup 1.0000x reference)
#include <cuda_runtime.h>
#include <math.h>

#define C_CH 8
#define NH 256
#define NW 256
#define OS 320
#define PAD 32
#define NPTS (64*4096)
#define PI_F 3.14159265358979323846

// ---------------- scratch (static device arrays; no allocation) ----------------
__device__ float2 d_W[OS*OS];                 // centered DFT matrix (symmetric)
__device__ float2 d_Ain[C_CH*NH*NW];          // apodized+scaled input
__device__ float2 d_T[C_CH*NH*OS];            // after row transform
__device__ float2 d_G[C_CH*OS*OS];            // full spectrum, channel-major
__device__ float2 d_P[OS*OS*C_CH];            // spectrum packed [y][x][c]

// ---------------- W matrix: W[k][m] = (-1)^(k+m) * exp(-2pi i k m / 320) ------
__global__ void build_w_kernel() {
    int idx = blockIdx.x * blockDim.x + threadIdx.x;
    if (idx >= OS*OS) return;
    int k = idx / OS, m = idx % OS;
    int r = (k * m) % OS;                 // exact angle reduction
    float s, c;
    sincospif(2.0f * (float)r / (float)OS, &s, &c);
    float sign = ((k + m) & 1) ? -1.0f : 1.0f;
    d_W[idx] = make_float2(sign * c, -sign * s);
}

// ---------------- apodization + 1/sqrt(HW) scale ------------------------------
__global__ void prep_kernel(const float* __restrict__ img_r,
                            const float* __restrict__ img_i,
                            float beta2) {
    int idx = blockIdx.x * blockDim.x + threadIdx.x;
    if (idx >= C_CH*NH*NW) return;
    int j = idx % NW;
    int h = (idx / NW) % NH;
    float u, arg, fh, fj;
    u   = (float)PI_F * 6.0f * (float)(h - 128) / 320.0f;
    arg = sqrtf(beta2 - u*u);
    fh  = arg / sinhf(arg);
    u   = (float)PI_F * 6.0f * (float)(j - 128) / 320.0f;
    arg = sqrtf(beta2 - u*u);
    fj  = arg / sinhf(arg);
    float s = fh * fj * (1.0f / 256.0f);   // 1/sqrt(256*256)
    d_Ain[idx] = make_float2(img_r[idx] * s, img_i[idx] * s);
}

// ---------------- tiled complex GEMM body (BM=BN=64, BK=16, 256 thr) ----------
__device__ __forceinline__ void cgemm_body(const float2* __restrict__ A, int lda,
                                           const float2* __restrict__ B, int ldb,
                                           float2* __restrict__ C, int ldc,
                                           int K, int amax, int bmax, int cmax) {
    __shared__ float2 As[16][66];   // [k][m]
    __shared__ float2 Bs[16][64];   // [k][n]
    const int tid = threadIdx.x;
    const int bm = blockIdx.y * 64;
    const int bn = blockIdx.x * 64;

    float2 acc[4][4];
#pragma unroll
    for (int i = 0; i < 4; i++)
#pragma unroll
        for (int j = 0; j < 4; j++) acc[i][j] = make_float2(0.f, 0.f);

    const int tm = (tid >> 4) << 2;
    const int tn = (tid & 15) << 2;
    const int ar = tid >> 4;          // 0..15
    const int ac = tid & 15;          // 0..15
    const int br = tid >> 6;          // 0..3
    const int bc = tid & 63;          // 0..63

    for (int k0 = 0; k0 < K; k0 += 16) {
#pragma unroll
        for (int p = 0; p < 4; p++) {
            int ia = (bm + ar + p*16) * lda + (k0 + ac);
            As[ac][ar + p*16] = A[min(ia, amax)];
        }
#pragma unroll
        for (int p = 0; p < 4; p++) {
            int ib = (k0 + br + p*4) * ldb + (bn + bc);
            Bs[br + p*4][bc] = B[min(ib, bmax)];
        }
        __syncthreads();
#pragma unroll
        for (int kk = 0; kk < 16; kk++) {
            float2 a[4], b[4];
#pragma unroll
            for (int i = 0; i < 4; i++) a[i] = As[kk][tm + i];
#pragma unroll
            for (int j = 0; j < 4; j++) b[j] = Bs[kk][tn + j];
#pragma unroll
            for (int i = 0; i < 4; i++)
#pragma unroll
                for (int j = 0; j < 4; j++) {
                    acc[i][j].x = fmaf( a[i].x, b[j].x, acc[i][j].x);
                    acc[i][j].x = fmaf(-a[i].y, b[j].y, acc[i][j].x);
                    acc[i][j].y = fmaf( a[i].x, b[j].y, acc[i][j].y);
                    acc[i][j].y = fmaf( a[i].y, b[j].x, acc[i][j].y);
                }
        }
        __syncthreads();
    }
#pragma unroll
    for (int i = 0; i < 4; i++)
#pragma unroll
        for (int j = 0; j < 4; j++) {
            int ic = (bm + tm + i) * ldc + (bn + tn + j);
            if (ic <= cmax) C[ic] = acc[i][j];
        }
}

// stage1: T[c][h][k] = sum_j Ain[c][h][j] * W[32+j][k]   (M=256, N=320, K=256)
__global__ void __launch_bounds__(256) stage1_kernel() {
    int c = blockIdx.z;
    cgemm_body(d_Ain + (size_t)c * NH * NW, NW,
               d_W + (size_t)PAD * OS,      OS,
               d_T + (size_t)c * NH * OS,   OS, NW,
               NH*NW - 1, OS*OS - PAD*OS - 1, NH*OS - 1);
}

// stage2: G[c][k2][k] = sum_h W[k2][32+h] * T[c][h][k]   (M=320, N=320, K=256)
__global__ void __launch_bounds__(256) stage2_kernel() {
    int c = blockIdx.z;
    cgemm_body(d_W + PAD,                   OS,
               d_T + (size_t)c * NH * OS,   OS,
               d_G + (size_t)c * OS * OS,   OS, NH,
               OS*OS - PAD - 1, NH*OS - 1, OS*OS - 1);
}

// ---------------- pack to [y][x][c] for contiguous per-point gathers ----------
__global__ void pack_kernel() {
    int idx = blockIdx.x * blockDim.x + threadIdx.x;
    if (idx >= C_CH*OS*OS) return;
    int c  = idx & 7;
    int yx = idx >> 3;
    d_P[idx] = d_G[(size_t)c * OS * OS + yx];
}

// ---------------- Kaiser-Bessel i0 (Abramowitz & Stegun 9.8.1 / 9.8.2) --------
__device__ __forceinline__ float i0f(float x) {
    if (x < 3.75f) {
        float t = x * (1.0f / 3.75f);
        t *= t;
        return 1.0f + t*(3.5156229f + t*(3.0899424f + t*(1.2067492f +
                     t*(0.2659732f + t*(0.0360768f + t*0.0045813f)))));
    } else {
        float t = 3.75f / x;
        float p = 0.39894228f + t*(0.01328592f + t*(0.00225319f +
                  t*(-0.00157565f + t*(0.00916281f + t*(-0.02057706f +
                  t*(0.02635537f + t*(-0.01647633f + t*0.00392377f)))))));
        return expf(x) * rsqrtf(x) * p;
    }
}

// ---------------- KB interpolation: 6x6 gather, 8 channels per point ----------
// Output: REAL PART ONLY, float32, layout [c][p], out_size floats total.
__global__ void interp_kernel(const float* __restrict__ trj,
                              float* __restrict__ out, float beta,
                              int out_floats) {
    int p = blockIdx.x * blockDim.x + threadIdx.x;
    if (p >= NPTS) return;
    float tx = trj[2*p], ty = trj[2*p + 1];
    float cx = __fadd_rn(__fmul_rn(tx, 1.25f), 160.0f);
    float cy = __fadd_rn(__fmul_rn(ty, 1.25f), 160.0f);
    float x0 = ceilf(cx - 3.0f);
    float y0 = ceilf(cy - 3.0f);

    float wx[6], wy[6];
    int   ox[6], oy[6];
#pragma unroll
    for (int d = 0; d < 6; d++) {
        float px = x0 + (float)d;
        float u  = (px - cx) / 3.0f;
        wx[d] = i0f(beta * sqrtf(fmaxf(1.0f - u*u, 0.0f)));
        int q = (int)px % OS; if (q < 0) q += OS;
        q = min(max(q, 0), OS - 1);
        ox[d] = q * (OS * C_CH);

        float py = y0 + (float)d;
        u = (py - cy) / 3.0f;
        wy[d] = i0f(beta * sqrtf(fmaxf(1.0f - u*u, 0.0f)));
        q = (int)py % OS; if (q < 0) q += OS;
        q = min(max(q, 0), OS - 1);
        oy[d] = q * C_CH;
    }

    float2 acc[8];
#pragma unroll
    for (int c = 0; c < 8; c++) acc[c] = make_float2(0.f, 0.f);

#pragma unroll 1
    for (int dx = 0; dx < 6; dx++) {
#pragma unroll
        for (int dy = 0; dy < 6; dy++) {
            float w = wx[dx] * wy[dy];
            int base = ox[dx] + oy[dy];
            base = min(base, OS*OS*C_CH - 8);
#pragma unroll
            for (int c = 0; c < 8; c++) {
                float2 v = __ldg(&d_P[base + c]);
                acc[c].x = fmaf(w, v.x, acc[c].x);
                acc[c].y = fmaf(w, v.y, acc[c].y);
            }
        }
    }

    const float inv36 = 1.0f / 36.0f;
#pragma unroll
    for (int c = 0; c < 8; c++) {
        int idx = c * NPTS + p;            // float32 element index (real part)
        if (idx < out_floats)
            out[idx] = acc[c].x * inv36;
    }
}

// ---------------- launch -------------------------------------------------------
extern "C" void kernel_launch(void* const* d_in, const int* in_sizes, int n_in,
                              void* d_out, int out_size) {
    // Inputs in setup_inputs order: img_r, img_i, trj
    const float* img_r = (const float*)d_in[0];
    const float* img_i = (const float*)d_in[1];
    const float* trj   = (const float*)d_in[2];
    float* out = (float*)d_out;

    double beta_d = PI_F * sqrt(12.16);   // pi*sqrt((6/1.25*0.75)^2 - 0.8)
    float beta  = (float)beta_d;
    float beta2 = (float)(beta_d * beta_d);

    build_w_kernel<<<(OS*OS + 255) / 256, 256>>>();
    prep_kernel<<<(C_CH*NH*NW + 255) / 256, 256>>>(img_r, img_i, beta2);

    dim3 g1(OS/64, NH/64, C_CH);   // (5,4,8)
    stage1_kernel<<<g1, 256>>>();
    dim3 g2(OS/64, OS/64, C_CH);   // (5,5,8)
    stage2_kernel<<<g2, 256>>>();

    pack_kernel<<<(C_CH*OS*OS + 255) / 256, 256>>>();
    interp_kernel<<<(NPTS + 255) / 256, 256>>>(trj, out, beta, out_size);
}

// round 5
// speedup vs baseline: 1.7118x; 1.7118x over previous
#include <cuda_runtime.h>
#include <math.h>

#define C_CH 8
#define NH 256
#define NW 256
#define OS 320
#define PAD 32
#define NPTS (64*4096)
#define PI_F 3.14159265358979323846

// ---------------- scratch (static device arrays; no allocation) ----------------
__device__ float2 d_W[OS*OS];                 // centered DFT matrix (symmetric)
__device__ float2 d_Ain[C_CH*NH*NW];          // apodized+scaled input
__device__ float2 d_T[C_CH*NH*OS];            // after row transform (complex)
__device__ __align__(16) float d_Pf[OS*OS*C_CH]; // re(spectrum), packed [y][x][c]

// ---------------- W matrix: W[k][m] = (-1)^(k+m) * exp(-2pi i k m / 320) ------
__global__ void build_w_kernel() {
    int idx = blockIdx.x * blockDim.x + threadIdx.x;
    if (idx >= OS*OS) return;
    int k = idx / OS, m = idx % OS;
    int r = (k * m) % OS;                 // exact angle reduction
    float s, c;
    sincospif(2.0f * (float)r / (float)OS, &s, &c);
    float sign = ((k + m) & 1) ? -1.0f : 1.0f;
    d_W[idx] = make_float2(sign * c, -sign * s);
}

// ---------------- apodization + 1/sqrt(HW) scale ------------------------------
__global__ void prep_kernel(const float* __restrict__ img_r,
                            const float* __restrict__ img_i,
                            float beta2) {
    int idx = blockIdx.x * blockDim.x + threadIdx.x;
    if (idx >= C_CH*NH*NW) return;
    int j = idx % NW;
    int h = (idx / NW) % NH;
    float u, arg, fh, fj;
    u   = (float)PI_F * 6.0f * (float)(h - 128) / 320.0f;
    arg = sqrtf(beta2 - u*u);
    fh  = arg / sinhf(arg);
    u   = (float)PI_F * 6.0f * (float)(j - 128) / 320.0f;
    arg = sqrtf(beta2 - u*u);
    fj  = arg / sinhf(arg);
    float s = fh * fj * (1.0f / 256.0f);   // 1/sqrt(256*256)
    d_Ain[idx] = make_float2(img_r[idx] * s, img_i[idx] * s);
}

// ---------------- stage1: full complex GEMM (BM=BN=64, BK=16, 256 thr) --------
// T[c][h][k] = sum_j Ain[c][h][j] * W[32+j][k]   (M=256, N=320, K=256)
__global__ void __launch_bounds__(256) stage1_kernel() {
    __shared__ float2 As[16][66];   // [k][m]
    __shared__ float2 Bs[16][64];   // [k][n]
    const int c   = blockIdx.z;
    const float2* A = d_Ain + (size_t)c * NH * NW;   // lda = NW
    const float2* B = d_W + (size_t)PAD * OS;        // ldb = OS
    float2*       Cm = d_T + (size_t)c * NH * OS;    // ldc = OS

    const int tid = threadIdx.x;
    const int bm = blockIdx.y * 64;
    const int bn = blockIdx.x * 64;

    float2 acc[4][4];
#pragma unroll
    for (int i = 0; i < 4; i++)
#pragma unroll
        for (int j = 0; j < 4; j++) acc[i][j] = make_float2(0.f, 0.f);

    const int tm = (tid >> 4) << 2;
    const int tn = (tid & 15) << 2;
    const int ar = tid >> 4, ac = tid & 15;
    const int br = tid >> 6, bc = tid & 63;

    for (int k0 = 0; k0 < NW; k0 += 16) {
#pragma unroll
        for (int p = 0; p < 4; p++) {
            int ia = (bm + ar + p*16) * NW + (k0 + ac);
            As[ac][ar + p*16] = A[min(ia, NH*NW - 1)];
        }
#pragma unroll
        for (int p = 0; p < 4; p++) {
            int ib = (k0 + br + p*4) * OS + (bn + bc);
            Bs[br + p*4][bc] = B[min(ib, OS*OS - PAD*OS - 1)];
        }
        __syncthreads();
#pragma unroll
        for (int kk = 0; kk < 16; kk++) {
            float2 a[4], b[4];
#pragma unroll
            for (int i = 0; i < 4; i++) a[i] = As[kk][tm + i];
#pragma unroll
            for (int j = 0; j < 4; j++) b[j] = Bs[kk][tn + j];
#pragma unroll
            for (int i = 0; i < 4; i++)
#pragma unroll
                for (int j = 0; j < 4; j++) {
                    acc[i][j].x = fmaf( a[i].x, b[j].x, acc[i][j].x);
                    acc[i][j].x = fmaf(-a[i].y, b[j].y, acc[i][j].x);
                    acc[i][j].y = fmaf( a[i].x, b[j].y, acc[i][j].y);
                    acc[i][j].y = fmaf( a[i].y, b[j].x, acc[i][j].y);
                }
        }
        __syncthreads();
    }
#pragma unroll
    for (int i = 0; i < 4; i++)
#pragma unroll
        for (int j = 0; j < 4; j++) {
            int ic = (bm + tm + i) * OS + (bn + tn + j);
            if (ic < NH*OS) Cm[ic] = acc[i][j];
        }
}

// ---------------- stage2: REAL-ONLY GEMM, fused pack --------------------------
// re(G[c][k2][k]) = sum_h [ Wr[k2][32+h]*Tr[c][h][k] - Wi[k2][32+h]*Ti[c][h][k] ]
// writes directly to d_Pf[(k2*OS + k)*8 + c]   (M=320, N=320, K=256)
__global__ void __launch_bounds__(256) stage2_kernel() {
    __shared__ float2 Ws[16][66];   // [h][m] (W rows tile)
    __shared__ float2 Ts[16][64];   // [h][n]
    const int c = blockIdx.z;
    const float2* A = d_W + PAD;                     // A[m][h] = W[m][32+h], lda = OS
    const float2* B = d_T + (size_t)c * NH * OS;     // B[h][n], ldb = OS

    const int tid = threadIdx.x;
    const int bm = blockIdx.y * 64;
    const int bn = blockIdx.x * 64;

    float acc[4][4];
#pragma unroll
    for (int i = 0; i < 4; i++)
#pragma unroll
        for (int j = 0; j < 4; j++) acc[i][j] = 0.f;

    const int tm = (tid >> 4) << 2;
    const int tn = (tid & 15) << 2;
    const int ar = tid >> 4, ac = tid & 15;
    const int br = tid >> 6, bc = tid & 63;

    for (int k0 = 0; k0 < NH; k0 += 16) {
#pragma unroll
        for (int p = 0; p < 4; p++) {
            int ia = (bm + ar + p*16) * OS + (k0 + ac);
            Ws[ac][ar + p*16] = A[min(ia, OS*OS - PAD - 1)];
        }
#pragma unroll
        for (int p = 0; p < 4; p++) {
            int ib = (k0 + br + p*4) * OS + (bn + bc);
            Ts[br + p*4][bc] = B[min(ib, NH*OS - 1)];
        }
        __syncthreads();
#pragma unroll
        for (int kk = 0; kk < 16; kk++) {
            float2 a[4], b[4];
#pragma unroll
            for (int i = 0; i < 4; i++) a[i] = Ws[kk][tm + i];
#pragma unroll
            for (int j = 0; j < 4; j++) b[j] = Ts[kk][tn + j];
#pragma unroll
            for (int i = 0; i < 4; i++)
#pragma unroll
                for (int j = 0; j < 4; j++) {
                    acc[i][j] = fmaf( a[i].x, b[j].x, acc[i][j]);
                    acc[i][j] = fmaf(-a[i].y, b[j].y, acc[i][j]);
                }
        }
        __syncthreads();
    }
#pragma unroll
    for (int i = 0; i < 4; i++)
#pragma unroll
        for (int j = 0; j < 4; j++) {
            int yx = (bm + tm + i) * OS + (bn + tn + j);
            int ip = yx * C_CH + c;
            if (ip < OS*OS*C_CH) d_Pf[ip] = acc[i][j];
        }
}

// ---------------- Kaiser-Bessel i0 (Abramowitz & Stegun 9.8.1 / 9.8.2) --------
__device__ __forceinline__ float i0f(float x) {
    if (x < 3.75f) {
        float t = x * (1.0f / 3.75f);
        t *= t;
        return 1.0f + t*(3.5156229f + t*(3.0899424f + t*(1.2067492f +
                     t*(0.2659732f + t*(0.0360768f + t*0.0045813f)))));
    } else {
        float t = 3.75f / x;
        float p = 0.39894228f + t*(0.01328592f + t*(0.00225319f +
                  t*(-0.00157565f + t*(0.00916281f + t*(-0.02057706f +
                  t*(0.02635537f + t*(-0.01647633f + t*0.00392377f)))))));
        return expf(x) * rsqrtf(x) * p;
    }
}

// ---------------- KB interpolation: 6x6 gather, 8 real channels per point -----
// Output: real part only, float32, layout [c][p]
__global__ void interp_kernel(const float* __restrict__ trj,
                              float* __restrict__ out, float beta,
                              int out_floats) {
    int p = blockIdx.x * blockDim.x + threadIdx.x;
    if (p >= NPTS) return;
    float tx = trj[2*p], ty = trj[2*p + 1];
    float cx = __fadd_rn(__fmul_rn(tx, 1.25f), 160.0f);
    float cy = __fadd_rn(__fmul_rn(ty, 1.25f), 160.0f);
    float x0 = ceilf(cx - 3.0f);
    float y0 = ceilf(cy - 3.0f);

    float wx[6], wy[6];
    int   ox[6], oy[6];
#pragma unroll
    for (int d = 0; d < 6; d++) {
        float px = x0 + (float)d;
        float u  = (px - cx) / 3.0f;
        wx[d] = i0f(beta * sqrtf(fmaxf(1.0f - u*u, 0.0f)));
        int q = (int)px % OS; if (q < 0) q += OS;
        ox[d] = q * (OS * C_CH);

        float py = y0 + (float)d;
        u = (py - cy) / 3.0f;
        wy[d] = i0f(beta * sqrtf(fmaxf(1.0f - u*u, 0.0f)));
        q = (int)py % OS; if (q < 0) q += OS;
        oy[d] = q * C_CH;
    }

    float acc[8];
#pragma unroll
    for (int c = 0; c < 8; c++) acc[c] = 0.f;

#pragma unroll 1
    for (int dx = 0; dx < 6; dx++) {
#pragma unroll
        for (int dy = 0; dy < 6; dy++) {
            float w = wx[dx] * wy[dy];
            int base = min(ox[dx] + oy[dy], OS*OS*C_CH - 8);
            const float4* g = reinterpret_cast<const float4*>(&d_Pf[base]);
            float4 v0 = __ldg(g);
            float4 v1 = __ldg(g + 1);
            acc[0] = fmaf(w, v0.x, acc[0]);
            acc[1] = fmaf(w, v0.y, acc[1]);
            acc[2] = fmaf(w, v0.z, acc[2]);
            acc[3] = fmaf(w, v0.w, acc[3]);
            acc[4] = fmaf(w, v1.x, acc[4]);
            acc[5] = fmaf(w, v1.y, acc[5]);
            acc[6] = fmaf(w, v1.z, acc[6]);
            acc[7] = fmaf(w, v1.w, acc[7]);
        }
    }

    const float inv36 = 1.0f / 36.0f;
#pragma unroll
    for (int c = 0; c < 8; c++) {
        int idx = c * NPTS + p;
        if (idx < out_floats) out[idx] = acc[c] * inv36;
    }
}

// ---------------- launch -------------------------------------------------------
extern "C" void kernel_launch(void* const* d_in, const int* in_sizes, int n_in,
                              void* d_out, int out_size) {
    const float* img_r = (const float*)d_in[0];
    const float* img_i = (const float*)d_in[1];
    const float* trj   = (const float*)d_in[2];
    float* out = (float*)d_out;

    double beta_d = PI_F * sqrt(12.16);   // pi*sqrt((6/1.25*0.75)^2 - 0.8)
    float beta  = (float)beta_d;
    float beta2 = (float)(beta_d * beta_d);

    build_w_kernel<<<(OS*OS + 255) / 256, 256>>>();
    prep_kernel<<<(C_CH*NH*NW + 255) / 256, 256>>>(img_r, img_i, beta2);

    dim3 g1(OS/64, NH/64, C_CH);   // (5,4,8)
    stage1_kernel<<<g1, 256>>>();
    dim3 g2(OS/64, OS/64, C_CH);   // (5,5,8)
    stage2_kernel<<<g2, 256>>>();

    interp_kernel<<<(NPTS + 255) / 256, 256>>>(trj, out, beta, out_size);
}

// round 6
// speedup vs baseline: 1.8814x; 1.0991x over previous
#include <cuda_runtime.h>
#include <math.h>

#define C_CH 8
#define NH 256
#define NW 256
#define OS 320
#define PAD 32
#define NPTS (64*4096)
#define PI_F 3.14159265358979323846

// ---------------- scratch (static device arrays; no allocation) ----------------
__device__ float2 d_W[OS*OS];                 // centered DFT matrix (symmetric)
__device__ float2 d_Ain[C_CH*NH*NW];          // apodized+scaled input
__device__ float2 d_T[C_CH*NH*OS];            // after row transform (complex)
__device__ __align__(16) float d_Pf[OS*OS*C_CH]; // re(spectrum), packed [y][x][c]

// ---------------- W matrix: W[k][m] = (-1)^(k+m) * exp(-2pi i k m / 320) ------
__global__ void build_w_kernel() {
    int idx = blockIdx.x * blockDim.x + threadIdx.x;
    if (idx >= OS*OS) return;
    int k = idx / OS, m = idx % OS;
    int r = (k * m) % OS;
    float s, c;
    sincospif(2.0f * (float)r / (float)OS, &s, &c);
    float sign = ((k + m) & 1) ? -1.0f : 1.0f;
    d_W[idx] = make_float2(sign * c, -sign * s);
}

// ---------------- apodization + 1/sqrt(HW) scale ------------------------------
__global__ void prep_kernel(const float* __restrict__ img_r,
                            const float* __restrict__ img_i,
                            float beta2) {
    int idx = blockIdx.x * blockDim.x + threadIdx.x;
    if (idx >= C_CH*NH*NW) return;
    int j = idx % NW;
    int h = (idx / NW) % NH;
    float u, arg, fh, fj;
    u   = (float)PI_F * 6.0f * (float)(h - 128) / 320.0f;
    arg = sqrtf(beta2 - u*u);
    fh  = arg / sinhf(arg);
    u   = (float)PI_F * 6.0f * (float)(j - 128) / 320.0f;
    arg = sqrtf(beta2 - u*u);
    fj  = arg / sinhf(arg);
    float s = fh * fj * (1.0f / 256.0f);
    d_Ain[idx] = make_float2(img_r[idx] * s, img_i[idx] * s);
}

// =================== stage1: complex GEMM, 64x64 tile, 128 thr =================
// T[c][h][k] = sum_j Ain[c][h][j] * W[32+j][k]   (M=256, N=320, K=256)
// thread tile 8x4 (strided: rows tmi+8i, cols tni+16j)
__global__ void __launch_bounds__(128) stage1_kernel() {
    __shared__ float2 As[16][65];   // [k][m], odd pad -> conflict-free STS
    __shared__ float2 Bs[16][64];   // [k][n]
    const int c = blockIdx.z;
    const float2* __restrict__ A = d_Ain + (size_t)c * NH * NW;  // lda=NW
    const float2* __restrict__ B = d_W + (size_t)PAD * OS;       // ldb=OS
    float2* __restrict__ Cm      = d_T + (size_t)c * NH * OS;    // ldc=OS

    const int tid = threadIdx.x;
    const int bm = blockIdx.y * 64;
    const int bn = blockIdx.x * 64;
    const int tmi = tid >> 4;     // 0..7
    const int tni = tid & 15;     // 0..15
    const int lak = tid & 15, lam = tid >> 4;   // A loader: k lane, m group
    const int lbn = tid & 63, lbh = tid >> 6;   // B loader: n lane, h group

    float2 acc[8][4];
#pragma unroll
    for (int i = 0; i < 8; i++)
#pragma unroll
        for (int j = 0; j < 4; j++) acc[i][j] = make_float2(0.f, 0.f);

    for (int k0 = 0; k0 < NW; k0 += 16) {
#pragma unroll
        for (int p = 0; p < 8; p++) {
            int m = lam + p*8;
            int ia = (bm + m) * NW + (k0 + lak);
            As[lak][m] = A[min(ia, NH*NW - 1)];
        }
#pragma unroll
        for (int p = 0; p < 8; p++) {
            int h = lbh + p*2;
            int ib = (k0 + h) * OS + (bn + lbn);
            Bs[h][lbn] = B[min(ib, OS*OS - PAD*OS - 1)];
        }
        __syncthreads();
#pragma unroll
        for (int kk = 0; kk < 16; kk++) {
            float2 a[8], b[4];
#pragma unroll
            for (int i = 0; i < 8; i++) a[i] = As[kk][tmi + 8*i];
#pragma unroll
            for (int j = 0; j < 4; j++) b[j] = Bs[kk][tni + 16*j];
#pragma unroll
            for (int i = 0; i < 8; i++)
#pragma unroll
                for (int j = 0; j < 4; j++) {
                    acc[i][j].x = fmaf( a[i].x, b[j].x, acc[i][j].x);
                    acc[i][j].x = fmaf(-a[i].y, b[j].y, acc[i][j].x);
                    acc[i][j].y = fmaf( a[i].x, b[j].y, acc[i][j].y);
                    acc[i][j].y = fmaf( a[i].y, b[j].x, acc[i][j].y);
                }
        }
        __syncthreads();
    }
#pragma unroll
    for (int i = 0; i < 8; i++)
#pragma unroll
        for (int j = 0; j < 4; j++) {
            int ic = (bm + tmi + 8*i) * OS + (bn + tni + 16*j);
            if (ic < NH*OS) Cm[ic] = acc[i][j];
        }
}

// =================== stage2: real-part GEMM, fused pack ========================
// re(G[c][k2][k]) = sum_h [Wr*Tr - Wi*Ti], written to d_Pf[(k2*OS+k)*8+c]
// (M=320, N=320, K=256), 64x64 tile, 128 thr, 8x4 strided thread tile
__global__ void __launch_bounds__(128) stage2_kernel() {
    __shared__ float2 Ws[16][65];   // [h][m]
    __shared__ float2 Ts[16][64];   // [h][n]
    const int c = blockIdx.z;
    const float2* __restrict__ A = d_W + PAD;                    // A[m][h], lda=OS
    const float2* __restrict__ B = d_T + (size_t)c * NH * OS;    // B[h][n], ldb=OS

    const int tid = threadIdx.x;
    const int bm = blockIdx.y * 64;
    const int bn = blockIdx.x * 64;
    const int tmi = tid >> 4;
    const int tni = tid & 15;
    const int lak = tid & 15, lam = tid >> 4;
    const int lbn = tid & 63, lbh = tid >> 6;

    float acc[8][4];
#pragma unroll
    for (int i = 0; i < 8; i++)
#pragma unroll
        for (int j = 0; j < 4; j++) acc[i][j] = 0.f;

    for (int k0 = 0; k0 < NH; k0 += 16) {
#pragma unroll
        for (int p = 0; p < 8; p++) {
            int m = lam + p*8;
            int ia = (bm + m) * OS + (k0 + lak);
            Ws[lak][m] = A[min(ia, OS*OS - PAD - 1)];
        }
#pragma unroll
        for (int p = 0; p < 8; p++) {
            int h = lbh + p*2;
            int ib = (k0 + h) * OS + (bn + lbn);
            Ts[h][lbn] = B[min(ib, NH*OS - 1)];
        }
        __syncthreads();
#pragma unroll
        for (int kk = 0; kk < 16; kk++) {
            float2 a[8], b[4];
#pragma unroll
            for (int i = 0; i < 8; i++) a[i] = Ws[kk][tmi + 8*i];
#pragma unroll
            for (int j = 0; j < 4; j++) b[j] = Ts[kk][tni + 16*j];
#pragma unroll
            for (int i = 0; i < 8; i++)
#pragma unroll
                for (int j = 0; j < 4; j++) {
                    acc[i][j] = fmaf( a[i].x, b[j].x, acc[i][j]);
                    acc[i][j] = fmaf(-a[i].y, b[j].y, acc[i][j]);
                }
        }
        __syncthreads();
    }
#pragma unroll
    for (int i = 0; i < 8; i++)
#pragma unroll
        for (int j = 0; j < 4; j++) {
            int yx = (bm + tmi + 8*i) * OS + (bn + tni + 16*j);
            int ip = yx * C_CH + c;
            if (ip < OS*OS*C_CH) d_Pf[ip] = acc[i][j];
        }
}

// ---------------- Kaiser-Bessel i0 (Abramowitz & Stegun 9.8.1 / 9.8.2) --------
__device__ __forceinline__ float i0f(float x) {
    if (x < 3.75f) {
        float t = x * (1.0f / 3.75f);
        t *= t;
        return 1.0f + t*(3.5156229f + t*(3.0899424f + t*(1.2067492f +
                     t*(0.2659732f + t*(0.0360768f + t*0.0045813f)))));
    } else {
        float t = 3.75f / x;
        float p = 0.39894228f + t*(0.01328592f + t*(0.00225319f +
                  t*(-0.00157565f + t*(0.00916281f + t*(-0.02057706f +
                  t*(0.02635537f + t*(-0.01647633f + t*0.00392377f)))))));
        return expf(x) * rsqrtf(x) * p;
    }
}

// ---------------- KB interpolation: 6x6 gather, 8 real channels per point -----
__global__ void interp_kernel(const float* __restrict__ trj,
                              float* __restrict__ out, float beta,
                              int out_floats) {
    int p = blockIdx.x * blockDim.x + threadIdx.x;
    if (p >= NPTS) return;
    float tx = trj[2*p], ty = trj[2*p + 1];
    float cx = __fadd_rn(__fmul_rn(tx, 1.25f), 160.0f);
    float cy = __fadd_rn(__fmul_rn(ty, 1.25f), 160.0f);
    float x0 = ceilf(cx - 3.0f);
    float y0 = ceilf(cy - 3.0f);

    float wx[6], wy[6];
    int   ox[6], oy[6];
#pragma unroll
    for (int d = 0; d < 6; d++) {
        float px = x0 + (float)d;
        float u  = (px - cx) / 3.0f;
        wx[d] = i0f(beta * sqrtf(fmaxf(1.0f - u*u, 0.0f)));
        int q = (int)px % OS; if (q < 0) q += OS;
        ox[d] = q * (OS * C_CH);

        float py = y0 + (float)d;
        u = (py - cy) / 3.0f;
        wy[d] = i0f(beta * sqrtf(fmaxf(1.0f - u*u, 0.0f)));
        q = (int)py % OS; if (q < 0) q += OS;
        oy[d] = q * C_CH;
    }

    float acc[8];
#pragma unroll
    for (int c = 0; c < 8; c++) acc[c] = 0.f;

#pragma unroll
    for (int dx = 0; dx < 6; dx++) {
#pragma unroll
        for (int dy = 0; dy < 6; dy++) {
            float w = wx[dx] * wy[dy];
            int base = min(ox[dx] + oy[dy], OS*OS*C_CH - 8);
            const float4* g = reinterpret_cast<const float4*>(&d_Pf[base]);
            float4 v0 = __ldg(g);
            float4 v1 = __ldg(g + 1);
            acc[0] = fmaf(w, v0.x, acc[0]);
            acc[1] = fmaf(w, v0.y, acc[1]);
            acc[2] = fmaf(w, v0.z, acc[2]);
            acc[3] = fmaf(w, v0.w, acc[3]);
            acc[4] = fmaf(w, v1.x, acc[4]);
            acc[5] = fmaf(w, v1.y, acc[5]);
            acc[6] = fmaf(w, v1.z, acc[6]);
            acc[7] = fmaf(w, v1.w, acc[7]);
        }
    }

    const float inv36 = 1.0f / 36.0f;
#pragma unroll
    for (int c = 0; c < 8; c++) {
        int idx = c * NPTS + p;
        if (idx < out_floats) out[idx] = acc[c] * inv36;
    }
}

// ---------------- launch -------------------------------------------------------
extern "C" void kernel_launch(void* const* d_in, const int* in_sizes, int n_in,
                              void* d_out, int out_size) {
    const float* img_r = (const float*)d_in[0];
    const float* img_i = (const float*)d_in[1];
    const float* trj   = (const float*)d_in[2];
    float* out = (float*)d_out;

    double beta_d = PI_F * sqrt(12.16);
    float beta  = (float)beta_d;
    float beta2 = (float)(beta_d * beta_d);

    build_w_kernel<<<(OS*OS + 255) / 256, 256>>>();
    prep_kernel<<<(C_CH*NH*NW + 255) / 256, 256>>>(img_r, img_i, beta2);

    dim3 g1(OS/64, NH/64, C_CH);   // (5,4,8) = 160 blocks, 128 thr
    stage1_kernel<<<g1, 128>>>();
    dim3 g2(OS/64, OS/64, C_CH);   // (5,5,8) = 200 blocks, 128 thr
    stage2_kernel<<<g2, 128>>>();

    interp_kernel<<<(NPTS + 255) / 256, 256>>>(trj, out, beta, out_size);
}

// round 7
// speedup vs baseline: 2.1905x; 1.1643x over previous
#include <cuda_runtime.h>
#include <math.h>

#define C_CH 8
#define NH 256
#define NW 256
#define OS 320
#define PAD 32
#define NPTS (64*4096)
#define PI_F 3.14159265358979323846

// ---------------- scratch (static device arrays; no allocation) ----------------
__device__ float2 d_W[OS*OS];                 // centered DFT matrix (symmetric)
__device__ float2 d_Ain[C_CH*NH*NW];          // apodized+scaled input
__device__ float2 d_T[C_CH*NH*OS];            // after row transform (complex)
__device__ __align__(16) float d_Pf[OS*OS*C_CH]; // re(spectrum), packed [y][x][c]

// ---------------- W matrix: W[k][m] = (-1)^(k+m) * exp(-2pi i k m / 320) ------
__global__ void build_w_kernel() {
    int idx = blockIdx.x * blockDim.x + threadIdx.x;
    if (idx >= OS*OS) return;
    int k = idx / OS, m = idx % OS;
    int r = (k * m) % OS;
    float s, c;
    sincospif(2.0f * (float)r / (float)OS, &s, &c);
    float sign = ((k + m) & 1) ? -1.0f : 1.0f;
    d_W[idx] = make_float2(sign * c, -sign * s);
}

// ---------------- apodization + 1/sqrt(HW) scale ------------------------------
__global__ void prep_kernel(const float* __restrict__ img_r,
                            const float* __restrict__ img_i,
                            float beta2) {
    int idx = blockIdx.x * blockDim.x + threadIdx.x;
    if (idx >= C_CH*NH*NW) return;
    int j = idx % NW;
    int h = (idx / NW) % NH;
    float u, arg, fh, fj;
    u   = (float)PI_F * 6.0f * (float)(h - 128) / 320.0f;
    arg = sqrtf(beta2 - u*u);
    fh  = arg / sinhf(arg);
    u   = (float)PI_F * 6.0f * (float)(j - 128) / 320.0f;
    arg = sqrtf(beta2 - u*u);
    fj  = arg / sinhf(arg);
    float s = fh * fj * (1.0f / 256.0f);
    d_Ain[idx] = make_float2(img_r[idx] * s, img_i[idx] * s);
}

// =================== stage1: complex GEMM, 32x64 tile, 128 thr =================
// T[c][h][k] = sum_j Ain[c][h][j] * W[32+j][k]   (M=256, N=320, K=256)
// thread tile 4x4 strided (rows tmi+8i, cols tni+16j); grid (5, 8, 8) = 320 blks
__global__ void __launch_bounds__(128) stage1_kernel() {
    __shared__ float2 As[16][33];   // [k][m], odd pad
    __shared__ float2 Bs[16][64];   // [k][n]
    const int c = blockIdx.z;
    const float2* __restrict__ A = d_Ain + (size_t)c * NH * NW;  // lda=NW
    const float2* __restrict__ B = d_W + (size_t)PAD * OS;       // ldb=OS
    float2* __restrict__ Cm      = d_T + (size_t)c * NH * OS;    // ldc=OS

    const int tid = threadIdx.x;
    const int bm = blockIdx.y * 32;
    const int bn = blockIdx.x * 64;
    const int tmi = tid >> 4;     // 0..7 -> rows tmi+8i (i<4)
    const int tni = tid & 15;     // 0..15 -> cols tni+16j (j<4)
    const int lak = tid & 15, lam = tid >> 4;   // A loader
    const int lbn = tid & 63, lbh = tid >> 6;   // B loader

    float2 acc[4][4];
#pragma unroll
    for (int i = 0; i < 4; i++)
#pragma unroll
        for (int j = 0; j < 4; j++) acc[i][j] = make_float2(0.f, 0.f);

    for (int k0 = 0; k0 < NW; k0 += 16) {
#pragma unroll
        for (int p = 0; p < 4; p++) {
            int m = lam + p*8;
            int ia = (bm + m) * NW + (k0 + lak);
            As[lak][m] = A[min(ia, NH*NW - 1)];
        }
#pragma unroll
        for (int p = 0; p < 8; p++) {
            int h = lbh + p*2;
            int ib = (k0 + h) * OS + (bn + lbn);
            Bs[h][lbn] = B[min(ib, OS*OS - PAD*OS - 1)];
        }
        __syncthreads();
#pragma unroll
        for (int kk = 0; kk < 16; kk++) {
            float2 a[4], b[4];
#pragma unroll
            for (int i = 0; i < 4; i++) a[i] = As[kk][tmi + 8*i];
#pragma unroll
            for (int j = 0; j < 4; j++) b[j] = Bs[kk][tni + 16*j];
#pragma unroll
            for (int i = 0; i < 4; i++)
#pragma unroll
                for (int j = 0; j < 4; j++) {
                    acc[i][j].x = fmaf( a[i].x, b[j].x, acc[i][j].x);
                    acc[i][j].x = fmaf(-a[i].y, b[j].y, acc[i][j].x);
                    acc[i][j].y = fmaf( a[i].x, b[j].y, acc[i][j].y);
                    acc[i][j].y = fmaf( a[i].y, b[j].x, acc[i][j].y);
                }
        }
        __syncthreads();
    }
#pragma unroll
    for (int i = 0; i < 4; i++)
#pragma unroll
        for (int j = 0; j < 4; j++) {
            int ic = (bm + tmi + 8*i) * OS + (bn + tni + 16*j);
            if (ic < NH*OS) Cm[ic] = acc[i][j];
        }
}

// =================== stage2: real-part GEMM, fused pack ========================
// re(G[c][k2][k]) = sum_h [Wr*Tr - Wi*Ti] -> d_Pf[(k2*OS+k)*8+c]
// (M=320, N=320, K=256), 32x64 tile, 128 thr; grid (5, 10, 8) = 400 blocks
__global__ void __launch_bounds__(128) stage2_kernel() {
    __shared__ float2 Ws[16][33];   // [h][m]
    __shared__ float2 Ts[16][64];   // [h][n]
    const int c = blockIdx.z;
    const float2* __restrict__ A = d_W + PAD;                    // A[m][h], lda=OS
    const float2* __restrict__ B = d_T + (size_t)c * NH * OS;    // B[h][n], ldb=OS

    const int tid = threadIdx.x;
    const int bm = blockIdx.y * 32;
    const int bn = blockIdx.x * 64;
    const int tmi = tid >> 4;
    const int tni = tid & 15;
    const int lak = tid & 15, lam = tid >> 4;
    const int lbn = tid & 63, lbh = tid >> 6;

    float acc[4][4];
#pragma unroll
    for (int i = 0; i < 4; i++)
#pragma unroll
        for (int j = 0; j < 4; j++) acc[i][j] = 0.f;

    for (int k0 = 0; k0 < NH; k0 += 16) {
#pragma unroll
        for (int p = 0; p < 4; p++) {
            int m = lam + p*8;
            int ia = (bm + m) * OS + (k0 + lak);
            Ws[lak][m] = A[min(ia, OS*OS - PAD - 1)];
        }
#pragma unroll
        for (int p = 0; p < 8; p++) {
            int h = lbh + p*2;
            int ib = (k0 + h) * OS + (bn + lbn);
            Ts[h][lbn] = B[min(ib, NH*OS - 1)];
        }
        __syncthreads();
#pragma unroll
        for (int kk = 0; kk < 16; kk++) {
            float2 a[4], b[4];
#pragma unroll
            for (int i = 0; i < 4; i++) a[i] = Ws[kk][tmi + 8*i];
#pragma unroll
            for (int j = 0; j < 4; j++) b[j] = Ts[kk][tni + 16*j];
#pragma unroll
            for (int i = 0; i < 4; i++)
#pragma unroll
                for (int j = 0; j < 4; j++) {
                    acc[i][j] = fmaf( a[i].x, b[j].x, acc[i][j]);
                    acc[i][j] = fmaf(-a[i].y, b[j].y, acc[i][j]);
                }
        }
        __syncthreads();
    }
#pragma unroll
    for (int i = 0; i < 4; i++)
#pragma unroll
        for (int j = 0; j < 4; j++) {
            int yx = (bm + tmi + 8*i) * OS + (bn + tni + 16*j);
            int ip = yx * C_CH + c;
            if (ip < OS*OS*C_CH) d_Pf[ip] = acc[i][j];
        }
}

// ---------------- Kaiser-Bessel i0 (Abramowitz & Stegun 9.8.1 / 9.8.2) --------
__device__ __forceinline__ float i0f(float x) {
    if (x < 3.75f) {
        float t = x * (1.0f / 3.75f);
        t *= t;
        return 1.0f + t*(3.5156229f + t*(3.0899424f + t*(1.2067492f +
                     t*(0.2659732f + t*(0.0360768f + t*0.0045813f)))));
    } else {
        float t = 3.75f / x;
        float p = 0.39894228f + t*(0.01328592f + t*(0.00225319f +
                  t*(-0.00157565f + t*(0.00916281f + t*(-0.02057706f +
                  t*(0.02635537f + t*(-0.01647633f + t*0.00392377f)))))));
        return expf(x) * rsqrtf(x) * p;
    }
}

// ---------------- KB interpolation: 6x6 gather, 8 real channels per point -----
__global__ void __launch_bounds__(256) interp_kernel(const float* __restrict__ trj,
                              float* __restrict__ out, float beta,
                              int out_floats) {
    int p = blockIdx.x * blockDim.x + threadIdx.x;
    if (p >= NPTS) return;
    float tx = trj[2*p], ty = trj[2*p + 1];
    float cx = __fadd_rn(__fmul_rn(tx, 1.25f), 160.0f);
    float cy = __fadd_rn(__fmul_rn(ty, 1.25f), 160.0f);
    float x0 = ceilf(cx - 3.0f);
    float y0 = ceilf(cy - 3.0f);

    float wx[6], wy[6];
    int   ox[6], oy[6];
#pragma unroll
    for (int d = 0; d < 6; d++) {
        float px = x0 + (float)d;
        float u  = (px - cx) / 3.0f;
        wx[d] = i0f(beta * sqrtf(fmaxf(1.0f - u*u, 0.0f)));
        int q = (int)px % OS; if (q < 0) q += OS;
        ox[d] = q * (OS * C_CH);

        float py = y0 + (float)d;
        u = (py - cy) / 3.0f;
        wy[d] = i0f(beta * sqrtf(fmaxf(1.0f - u*u, 0.0f)));
        q = (int)py % OS; if (q < 0) q += OS;
        oy[d] = q * C_CH;
    }

    float acc[8];
#pragma unroll
    for (int c = 0; c < 8; c++) acc[c] = 0.f;

#pragma unroll
    for (int dx = 0; dx < 6; dx++) {
#pragma unroll
        for (int dy = 0; dy < 6; dy++) {
            float w = wx[dx] * wy[dy];
            int base = min(ox[dx] + oy[dy], OS*OS*C_CH - 8);
            const float4* g = reinterpret_cast<const float4*>(&d_Pf[base]);
            float4 v0 = __ldg(g);
            float4 v1 = __ldg(g + 1);
            acc[0] = fmaf(w, v0.x, acc[0]);
            acc[1] = fmaf(w, v0.y, acc[1]);
            acc[2] = fmaf(w, v0.z, acc[2]);
            acc[3] = fmaf(w, v0.w, acc[3]);
            acc[4] = fmaf(w, v1.x, acc[4]);
            acc[5] = fmaf(w, v1.y, acc[5]);
            acc[6] = fmaf(w, v1.z, acc[6]);
            acc[7] = fmaf(w, v1.w, acc[7]);
        }
    }

    const float inv36 = 1.0f / 36.0f;
#pragma unroll
    for (int c = 0; c < 8; c++) {
        int idx = c * NPTS + p;
        if (idx < out_floats) out[idx] = acc[c] * inv36;
    }
}

// ---------------- launch -------------------------------------------------------
extern "C" void kernel_launch(void* const* d_in, const int* in_sizes, int n_in,
                              void* d_out, int out_size) {
    const float* img_r = (const float*)d_in[0];
    const float* img_i = (const float*)d_in[1];
    const float* trj   = (const float*)d_in[2];
    float* out = (float*)d_out;

    double beta_d = PI_F * sqrt(12.16);
    float beta  = (float)beta_d;
    float beta2 = (float)(beta_d * beta_d);

    build_w_kernel<<<(OS*OS + 255) / 256, 256>>>();
    prep_kernel<<<(C_CH*NH*NW + 255) / 256, 256>>>(img_r, img_i, beta2);

    dim3 g1(OS/64, NH/32, C_CH);   // (5, 8, 8) = 320 blocks
    stage1_kernel<<<g1, 128>>>();
    dim3 g2(OS/64, OS/32, C_CH);   // (5, 10, 8) = 400 blocks
    stage2_kernel<<<g2, 128>>>();

    interp_kernel<<<(NPTS + 255) / 256, 256>>>(trj, out, beta, out_size);
}